// round 1
// baseline (speedup 1.0000x reference)
#include <cuda_runtime.h>

#define NT 16384      // tokens
#define MD 4096       // model dim
#define EM 128        // max experts
#define BM 128        // tokens per GEMM block
#define DK 32         // d-chunk per tile iteration
#define BMP 132       // padded token pitch (float4-aligned)
#define EP  130       // padded expert pitch (float2-aligned)
#define THRESH 0.5f

// ---------------------------------------------------------------------------
// GEMM + compaction: computes raw logits for ACTIVE experts only, scattered
// into out[token*128 + global_expert_id]. Masked expert slots left untouched
// (epilogue never reads them thanks to the mask).
// Template EC = ceil(n_active/32); non-matching instantiations return early.
// ---------------------------------------------------------------------------
template <int EC>
__global__ __launch_bounds__(256, 1)
void gemm_gate(const float* __restrict__ x, const float* __restrict__ wg,
               const float* __restrict__ mask, float* __restrict__ out) {
    __shared__ __align__(16) float xs[DK][BMP];
    __shared__ __align__(16) float ws[DK][EP];
    __shared__ int s_idx[EM];
    __shared__ int s_wcnt[8];
    __shared__ int s_nact;

    const int tid  = threadIdx.x;
    const int lane = tid & 31;
    const int wid  = tid >> 5;

    // ---- per-block mask compaction (cheap: 128 elems) ----
    bool act = false;
    if (tid < EM) act = (mask[tid] != 0.0f);
    unsigned b = __ballot_sync(0xffffffffu, act);
    if (lane == 0) s_wcnt[wid] = __popc(b);
    __syncthreads();
    {
        int ofs = 0;
        for (int i = 0; i < wid; i++) ofs += s_wcnt[i];
        int pos = ofs + __popc(b & ((1u << lane) - 1u));
        if (act) s_idx[pos] = tid;
        if (tid == 0) {
            int t = 0;
            for (int i = 0; i < 8; i++) t += s_wcnt[i];
            s_nact = t;
        }
    }
    __syncthreads();
    const int nact = s_nact;
    const int ec = (nact + 31) >> 5;
    if (ec != EC) return;   // uniform: dispatch to matching template only

    // thread tile: 8 tokens x (2*EC) experts
    const int tx = tid & 15;   // expert-pair group 0..15 (covers 32 experts/chunk)
    const int ty = tid >> 4;   // token group 0..15 (8 tokens each)
    const int tok0 = blockIdx.x * BM;

    float acc[EC][8][2];
#pragma unroll
    for (int c = 0; c < EC; c++)
#pragma unroll
        for (int i = 0; i < 8; i++) { acc[c][i][0] = 0.f; acc[c][i][1] = 0.f; }

    for (int d0 = 0; d0 < MD; d0 += DK) {
        __syncthreads();
        // load x tile (transposed): xs[d][token]
#pragma unroll
        for (int r = 0; r < 16; r++) {
            int t = wid * 16 + r;
            xs[lane][t] = x[(size_t)(tok0 + t) * MD + d0 + lane];
        }
        // load compacted w tile (transposed): ws[d][compact_e], zero-pad tail
#pragma unroll
        for (int r8 = 0; r8 < EC * 4; r8++) {
            int r = wid + r8 * 8;
            float v = 0.f;
            if (r < nact) v = wg[(size_t)s_idx[r] * MD + d0 + lane];
            ws[lane][r] = v;
        }
        __syncthreads();

#pragma unroll 8
        for (int dk = 0; dk < DK; dk++) {
            float4 xa = *(const float4*)&xs[dk][ty * 8];
            float4 xb = *(const float4*)&xs[dk][ty * 8 + 4];
#pragma unroll
            for (int c = 0; c < EC; c++) {
                float2 wv = *(const float2*)&ws[dk][c * 32 + tx * 2];
                acc[c][0][0] += xa.x * wv.x; acc[c][0][1] += xa.x * wv.y;
                acc[c][1][0] += xa.y * wv.x; acc[c][1][1] += xa.y * wv.y;
                acc[c][2][0] += xa.z * wv.x; acc[c][2][1] += xa.z * wv.y;
                acc[c][3][0] += xa.w * wv.x; acc[c][3][1] += xa.w * wv.y;
                acc[c][4][0] += xb.x * wv.x; acc[c][4][1] += xb.x * wv.y;
                acc[c][5][0] += xb.y * wv.x; acc[c][5][1] += xb.y * wv.y;
                acc[c][6][0] += xb.z * wv.x; acc[c][6][1] += xb.z * wv.y;
                acc[c][7][0] += xb.w * wv.x; acc[c][7][1] += xb.w * wv.y;
            }
        }
    }

    // scatter raw logits to out[token*EM + global_expert]
#pragma unroll
    for (int c = 0; c < EC; c++) {
#pragma unroll
        for (int j = 0; j < 2; j++) {
            int ce = c * 32 + tx * 2 + j;
            if (ce < nact) {
                int gid = s_idx[ce];
#pragma unroll
                for (int i = 0; i < 8; i++)
                    out[(size_t)(tok0 + ty * 8 + i) * EM + gid] = acc[c][i][j];
            }
        }
    }
}

// ---------------------------------------------------------------------------
// Epilogue: per warp = one token. Masked softmax (+1e-14), write scores,
// bitonic-sort 128 values descending, cumsum threshold -> top_k.
// ---------------------------------------------------------------------------
__global__ __launch_bounds__(256)
void gate_epilogue(const float* __restrict__ mask, float* __restrict__ out,
                   float* __restrict__ tk_out, int write_tk) {
    __shared__ float ss[8][128];
    const int lane = threadIdx.x & 31;
    const int wid  = threadIdx.x >> 5;
    const int n = blockIdx.x * 8 + wid;

    float4 v  = *(const float4*)&out[(size_t)n * EM + lane * 4];
    float4 mk = *(const float4*)&mask[lane * 4];

    float z0 = (mk.x != 0.f) ? v.x : -1e9f;
    float z1 = (mk.y != 0.f) ? v.y : -1e9f;
    float z2 = (mk.z != 0.f) ? v.z : -1e9f;
    float z3 = (mk.w != 0.f) ? v.w : -1e9f;

    int actc = (mk.x != 0.f) + (mk.y != 0.f) + (mk.z != 0.f) + (mk.w != 0.f);
#pragma unroll
    for (int o = 16; o > 0; o >>= 1) actc += __shfl_xor_sync(0xffffffffu, actc, o);

    float m = fmaxf(fmaxf(z0, z1), fmaxf(z2, z3));
#pragma unroll
    for (int o = 16; o > 0; o >>= 1) m = fmaxf(m, __shfl_xor_sync(0xffffffffu, m, o));

    float e0 = expf(z0 - m), e1 = expf(z1 - m), e2 = expf(z2 - m), e3 = expf(z3 - m);
    float s = e0 + e1 + e2 + e3;
#pragma unroll
    for (int o = 16; o > 0; o >>= 1) s += __shfl_xor_sync(0xffffffffu, s, o);

    float p0 = e0 / s + 1e-14f;
    float p1 = e1 / s + 1e-14f;
    float p2 = e2 / s + 1e-14f;
    float p3 = e3 / s + 1e-14f;

    float4 ov; ov.x = p0; ov.y = p1; ov.z = p2; ov.w = p3;
    *(float4*)&out[(size_t)n * EM + lane * 4] = ov;

    // sort (descending) in shared memory
    ss[wid][lane * 4 + 0] = p0;
    ss[wid][lane * 4 + 1] = p1;
    ss[wid][lane * 4 + 2] = p2;
    ss[wid][lane * 4 + 3] = p3;
    __syncwarp();

    for (int k = 2; k <= 128; k <<= 1) {
        for (int j = k >> 1; j > 0; j >>= 1) {
#pragma unroll
            for (int t = 0; t < 4; t++) {
                int i  = lane + t * 32;
                int ix = i ^ j;
                if (ix > i) {
                    float a = ss[wid][i], bb = ss[wid][ix];
                    bool desc = ((i & k) == 0);
                    if (desc ? (a < bb) : (a > bb)) { ss[wid][i] = bb; ss[wid][ix] = a; }
                }
            }
            __syncwarp();
        }
    }

    // cumsum over sorted values, count prefix-excl < THRESH
    float s0 = ss[wid][lane * 4 + 0];
    float s1 = ss[wid][lane * 4 + 1];
    float s2 = ss[wid][lane * 4 + 2];
    float s3 = ss[wid][lane * 4 + 3];
    float c0 = s0, c1 = c0 + s1, c2 = c1 + s2, c3 = c2 + s3;
    float ex = c3;
#pragma unroll
    for (int o = 1; o < 32; o <<= 1) {
        float t = __shfl_up_sync(0xffffffffu, ex, o);
        if (lane >= o) ex += t;
    }
    ex -= c3;  // exclusive prefix across lanes

    int cnt = (ex < THRESH) + (ex + c0 < THRESH) + (ex + c1 < THRESH) + (ex + c2 < THRESH);
#pragma unroll
    for (int o = 16; o > 0; o >>= 1) cnt += __shfl_xor_sync(0xffffffffu, cnt, o);

    if (lane == 0 && write_tk) {
        int tk = cnt < actc ? cnt : actc;
        tk_out[n] = (float)tk;
    }
}

extern "C" void kernel_launch(void* const* d_in, const int* in_sizes, int n_in,
                              void* d_out, int out_size) {
    const float* x    = (const float*)d_in[0];
    const float* wg   = (const float*)d_in[1];
    const float* mask = (const float*)d_in[2];
    float* out = (float*)d_out;
    float* tk  = out + (size_t)NT * EM;
    int write_tk = (out_size >= NT * EM + NT) ? 1 : 0;

    gemm_gate<1><<<NT / BM, 256>>>(x, wg, mask, out);
    gemm_gate<2><<<NT / BM, 256>>>(x, wg, mask, out);
    gemm_gate<3><<<NT / BM, 256>>>(x, wg, mask, out);
    gemm_gate<4><<<NT / BM, 256>>>(x, wg, mask, out);
    gate_epilogue<<<NT / 8, 256>>>(mask, out, tk, write_tk);
}

// round 5
// speedup vs baseline: 2.2741x; 2.2741x over previous
#include <cuda_runtime.h>
#include <cstdint>

#define NT 16384
#define MD 4096
#define EM 128
#define BM 128
#define BK 32
#define NCHUNK (MD / BK)   // 128
#define THRESH 0.5f
#define EPS_MARGIN 3e-4f

#define XST 36             // smem row stride (floats)
#define XBUF (BM * XST)    // 4608 floats per X stage
#define WBUF (64 * XST)    // 2304 floats per W stage (per hi/lo)

// ---------------- device scratch ----------------
__device__ float g_wc [EM * MD];   // compacted exact fp32 W (for repair)
__device__ float g_whi[EM * MD];   // compacted tf32-hi W
__device__ float g_wlo[EM * MD];   // compacted tf32-lo W
__device__ int   g_idx[EM];
__device__ int   g_nact;
__device__ int   g_nrep;
__device__ int   g_replist[NT];

// ---------------- helpers ----------------
__device__ __forceinline__ uint32_t smem_u32(const void* p) {
    uint32_t a;
    asm("{ .reg .u64 t; cvta.to.shared.u64 t, %1; cvt.u32.u64 %0, t; }" : "=r"(a) : "l"(p));
    return a;
}

#define CPA16(dst, src) \
    asm volatile("cp.async.cg.shared.global [%0], [%1], 16;" :: "r"(dst), "l"(src))
#define CPA_COMMIT() asm volatile("cp.async.commit_group;" ::: "memory")
#define CPA_WAIT(n)  asm volatile("cp.async.wait_group %0;" :: "n"(n) : "memory")

__device__ __forceinline__ void split_tf32(float v, uint32_t& hi, uint32_t& lo) {
    asm("cvt.rna.tf32.f32 %0, %1;" : "=r"(hi) : "f"(v));
    float l = v - __uint_as_float(hi);
    asm("cvt.rna.tf32.f32 %0, %1;" : "=r"(lo) : "f"(l));
}

#define MMA8(D, A, B0, B1)                                                     \
    asm volatile("mma.sync.aligned.m16n8k8.row.col.f32.tf32.tf32.f32 "         \
        "{%0,%1,%2,%3}, {%4,%5,%6,%7}, {%8,%9}, {%0,%1,%2,%3};"                \
        : "+f"((D)[0]), "+f"((D)[1]), "+f"((D)[2]), "+f"((D)[3])               \
        : "r"((A)[0]), "r"((A)[1]), "r"((A)[2]), "r"((A)[3]), "r"(B0), "r"(B1))

// ---------------- prep 1: mask compaction (+ zero repair queue) ----------------
__global__ void prep_compact(const float* __restrict__ mask) {
    __shared__ int cnts[4];
    int t = threadIdx.x, lane = t & 31, w = t >> 5;   // 128 threads
    bool a = (mask[t] != 0.0f);
    unsigned b = __ballot_sync(0xffffffffu, a);
    if (lane == 0) cnts[w] = __popc(b);
    __syncthreads();
    int ofs = 0;
    for (int i = 0; i < w; i++) ofs += cnts[i];
    if (a) g_idx[ofs + __popc(b & ((1u << lane) - 1u))] = t;
    if (t == 0) {
        g_nact = cnts[0] + cnts[1] + cnts[2] + cnts[3];
        g_nrep = 0;
    }
}

// ---------------- prep 2: compact + tf32 hi/lo split of W ----------------
__global__ __launch_bounds__(256)
void prep_split(const float* __restrict__ wg) {
    int e = blockIdx.x;
    int nact = g_nact;
    int t = threadIdx.x;
    float* dc = g_wc  + (size_t)e * MD;
    float* dh = g_whi + (size_t)e * MD;
    float* dl = g_wlo + (size_t)e * MD;
    if (e < nact) {
        const float* s = wg + (size_t)g_idx[e] * MD;
        for (int j = t * 4; j < MD; j += 1024) {
            float4 v = *(const float4*)(s + j);
            uint4 h, l;
            split_tf32(v.x, h.x, l.x);
            split_tf32(v.y, h.y, l.y);
            split_tf32(v.z, h.z, l.z);
            split_tf32(v.w, h.w, l.w);
            *(float4*)(dc + j) = v;
            *(uint4*)(dh + j) = h;
            *(uint4*)(dl + j) = l;
        }
    } else {
        float4 z = {0.f, 0.f, 0.f, 0.f};
        for (int j = t * 4; j < MD; j += 1024) {
            *(float4*)(dc + j) = z;
            *(float4*)(dh + j) = z;
            *(float4*)(dl + j) = z;
        }
    }
}

// ---------------- main GEMM (nact<=64): tf32x3, structured accumulation ----------------
__global__ __launch_bounds__(256, 1)
void gemm_mma64(const float* __restrict__ x, float* __restrict__ out) {
    const int nact = g_nact;
    if (nact > 64) return;

    extern __shared__ float sm[];
    __shared__ int s_idx[64];
    float* xs = sm;                         // [2][XBUF]
    float* wh = sm + 2 * XBUF;              // [2][WBUF]
    float* wl = sm + 2 * XBUF + 2 * WBUF;   // [2][WBUF]

    const int tid  = threadIdx.x;           // 256
    const int lane = tid & 31;
    const int wid  = tid >> 5;
    const int gid  = lane >> 2;
    const int tig  = lane & 3;
    const int tok0 = blockIdx.x * BM;

    if (tid < 64) s_idx[tid] = g_idx[tid];

    const int wm = wid & 3, wn = wid >> 2;
    const int mrow = wm * 32;
    const int ncol = wn * 32;                // 2 n-warps x 32 cols

    const uint32_t xsb = smem_u32(sm);
    const uint32_t whb = xsb + 2 * XBUF * 4;
    const uint32_t wlb = whb + 2 * WBUF * 4;

    float acc_s[2][4][4], acc_h[2][4][4], acc_l[2][4][4];
#pragma unroll
    for (int t = 0; t < 2; t++)
#pragma unroll
        for (int u = 0; u < 4; u++)
#pragma unroll
            for (int r = 0; r < 4; r++) {
                acc_s[t][u][r] = 0.f; acc_h[t][u][r] = 0.f; acc_l[t][u][r] = 0.f;
            }

#define LOAD_CHUNK(i) do {                                                    \
        const int b_ = (i) & 1;                                               \
        const uint32_t xd_ = xsb + b_ * (XBUF * 4);                           \
        const float* xsrc_ = x + (size_t)tok0 * MD + (i) * BK;                \
        _Pragma("unroll")                                                     \
        for (int q = 0; q < 4; q++) {                                         \
            int seg = tid + q * 256;                                          \
            int r = seg >> 3, c = seg & 7;                                    \
            CPA16(xd_ + r * 144 + c * 16, xsrc_ + (size_t)r * MD + c * 4);    \
        }                                                                     \
        _Pragma("unroll")                                                     \
        for (int q = 0; q < 2; q++) {                                         \
            int seg = tid + q * 256;                                          \
            int r = seg >> 3, c = seg & 7;                                    \
            CPA16(whb + b_ * (WBUF * 4) + r * 144 + c * 16,                   \
                  g_whi + (size_t)r * MD + (i) * BK + c * 4);                 \
            CPA16(wlb + b_ * (WBUF * 4) + r * 144 + c * 16,                   \
                  g_wlo + (size_t)r * MD + (i) * BK + c * 4);                 \
        }                                                                     \
        CPA_COMMIT();                                                         \
    } while (0)

    LOAD_CHUNK(0);
    __syncthreads();

    for (int i = 0; i < NCHUNK; i++) {
        if (i + 1 < NCHUNK) { LOAD_CHUNK(i + 1); CPA_WAIT(1); }
        else                { CPA_WAIT(0); }
        __syncthreads();

        const float* xb  = xs + (i & 1) * XBUF;
        const float* whp = wh + (i & 1) * WBUF;
        const float* wlp = wl + (i & 1) * WBUF;

#pragma unroll
        for (int kk = 0; kk < 4; kk++) {
            const int k = kk * 8;
            uint32_t ahi[2][4], alo[2][4];
#pragma unroll
            for (int t = 0; t < 2; t++) {
                const int r0 = mrow + t * 16;
                split_tf32(xb[(r0 + gid)     * XST + k + tig],     ahi[t][0], alo[t][0]);
                split_tf32(xb[(r0 + gid + 8) * XST + k + tig],     ahi[t][1], alo[t][1]);
                split_tf32(xb[(r0 + gid)     * XST + k + tig + 4], ahi[t][2], alo[t][2]);
                split_tf32(xb[(r0 + gid + 8) * XST + k + tig + 4], ahi[t][3], alo[t][3]);
            }
#pragma unroll
            for (int u = 0; u < 4; u++) {
                const int c0 = ncol + u * 8;
                uint32_t bh0 = __float_as_uint(whp[(c0 + gid) * XST + k + tig]);
                uint32_t bh1 = __float_as_uint(whp[(c0 + gid) * XST + k + tig + 4]);
                uint32_t bl0 = __float_as_uint(wlp[(c0 + gid) * XST + k + tig]);
                uint32_t bl1 = __float_as_uint(wlp[(c0 + gid) * XST + k + tig + 4]);
#pragma unroll
                for (int t = 0; t < 2; t++) {
                    MMA8(acc_h[t][u], ahi[t], bh0, bh1);   // hi*hi -> big acc
                    MMA8(acc_l[t][u], ahi[t], bl0, bl1);   // hi*lo -> small acc
                    MMA8(acc_l[t][u], alo[t], bh0, bh1);   // lo*hi -> small acc
                }
            }
        }
        if ((i & 7) == 7) {   // drain: short rounding chains in the big accumulator
#pragma unroll
            for (int t = 0; t < 2; t++)
#pragma unroll
                for (int u = 0; u < 4; u++)
#pragma unroll
                    for (int r = 0; r < 4; r++) {
                        acc_s[t][u][r] += acc_h[t][u][r];
                        acc_h[t][u][r] = 0.f;
                    }
        }
        __syncthreads();
    }

    // scatter raw logits
#pragma unroll
    for (int t = 0; t < 2; t++) {
        const int tokA = tok0 + mrow + t * 16 + gid;
#pragma unroll
        for (int u = 0; u < 4; u++) {
            const int e0 = ncol + u * 8 + tig * 2;
            float v0 = acc_s[t][u][0] + acc_h[t][u][0] + acc_l[t][u][0];
            float v1 = acc_s[t][u][1] + acc_h[t][u][1] + acc_l[t][u][1];
            float v2 = acc_s[t][u][2] + acc_h[t][u][2] + acc_l[t][u][2];
            float v3 = acc_s[t][u][3] + acc_h[t][u][3] + acc_l[t][u][3];
            if (e0 < nact) {
                const int g = s_idx[e0];
                out[(size_t)tokA * EM + g]       = v0;
                out[(size_t)(tokA + 8) * EM + g] = v2;
            }
            if (e0 + 1 < nact) {
                const int g = s_idx[e0 + 1];
                out[(size_t)tokA * EM + g]       = v1;
                out[(size_t)(tokA + 8) * EM + g] = v3;
            }
        }
    }
#undef LOAD_CHUNK
}

// ---------------- fallback GEMM (64 < nact <= 128): exact fp32 FFMA ----------------
template <int EC>
__global__ __launch_bounds__(256, 1)
void gemm_gate(const float* __restrict__ x, float* __restrict__ out) {
    const int nact = g_nact;
    const int ec = (nact + 31) >> 5;
    if (ec != EC || nact <= 64) return;

    __shared__ __align__(16) float xs[BK][132];
    __shared__ __align__(16) float ws[BK][130];
    __shared__ int s_idx[EM];

    const int tid  = threadIdx.x;
    const int lane = tid & 31;
    const int wid  = tid >> 5;
    if (tid < EM) s_idx[tid] = g_idx[tid];

    const int tx = tid & 15, ty = tid >> 4;
    const int tok0 = blockIdx.x * BM;

    float acc[EC][8][2];
#pragma unroll
    for (int c = 0; c < EC; c++)
#pragma unroll
        for (int i = 0; i < 8; i++) { acc[c][i][0] = 0.f; acc[c][i][1] = 0.f; }

    for (int d0 = 0; d0 < MD; d0 += BK) {
        __syncthreads();
#pragma unroll
        for (int r = 0; r < 16; r++) {
            int t = wid * 16 + r;
            xs[lane][t] = x[(size_t)(tok0 + t) * MD + d0 + lane];
        }
#pragma unroll
        for (int r8 = 0; r8 < EC * 4; r8++) {
            int r = wid + r8 * 8;
            ws[lane][r] = (r < nact) ? g_wc[(size_t)r * MD + d0 + lane] : 0.f;
        }
        __syncthreads();
#pragma unroll 8
        for (int dk = 0; dk < BK; dk++) {
            float4 xa = *(const float4*)&xs[dk][ty * 8];
            float4 xb = *(const float4*)&xs[dk][ty * 8 + 4];
#pragma unroll
            for (int c = 0; c < EC; c++) {
                float2 wv = *(const float2*)&ws[dk][c * 32 + tx * 2];
                acc[c][0][0] += xa.x * wv.x; acc[c][0][1] += xa.x * wv.y;
                acc[c][1][0] += xa.y * wv.x; acc[c][1][1] += xa.y * wv.y;
                acc[c][2][0] += xa.z * wv.x; acc[c][2][1] += xa.z * wv.y;
                acc[c][3][0] += xa.w * wv.x; acc[c][3][1] += xa.w * wv.y;
                acc[c][4][0] += xb.x * wv.x; acc[c][4][1] += xb.x * wv.y;
                acc[c][5][0] += xb.y * wv.x; acc[c][5][1] += xb.y * wv.y;
                acc[c][6][0] += xb.z * wv.x; acc[c][6][1] += xb.z * wv.y;
                acc[c][7][0] += xb.w * wv.x; acc[c][7][1] += xb.w * wv.y;
            }
        }
    }
#pragma unroll
    for (int c = 0; c < EC; c++)
#pragma unroll
        for (int j = 0; j < 2; j++) {
            int ce = c * 32 + tx * 2 + j;
            if (ce < nact) {
                int gid = s_idx[ce];
#pragma unroll
                for (int i = 0; i < 8; i++)
                    out[(size_t)(tok0 + ty * 8 + i) * EM + gid] = acc[c][i][j];
            }
        }
}

// ---------------- epilogue: softmax + sort + top-k, flag borderline tokens ----------------
__global__ __launch_bounds__(256)
void gate_epilogue(const float* __restrict__ mask, float* __restrict__ out,
                   float* __restrict__ tk_out, int write_tk) {
    __shared__ float ss[8][128];
    const int lane = threadIdx.x & 31;
    const int wid  = threadIdx.x >> 5;
    const int n = blockIdx.x * 8 + wid;

    float4 v  = *(const float4*)&out[(size_t)n * EM + lane * 4];
    float4 mk = *(const float4*)&mask[lane * 4];

    float z0 = (mk.x != 0.f) ? v.x : -1e9f;
    float z1 = (mk.y != 0.f) ? v.y : -1e9f;
    float z2 = (mk.z != 0.f) ? v.z : -1e9f;
    float z3 = (mk.w != 0.f) ? v.w : -1e9f;

    int actc = (mk.x != 0.f) + (mk.y != 0.f) + (mk.z != 0.f) + (mk.w != 0.f);
#pragma unroll
    for (int o = 16; o > 0; o >>= 1) actc += __shfl_xor_sync(0xffffffffu, actc, o);

    float m = fmaxf(fmaxf(z0, z1), fmaxf(z2, z3));
#pragma unroll
    for (int o = 16; o > 0; o >>= 1) m = fmaxf(m, __shfl_xor_sync(0xffffffffu, m, o));

    float e0 = expf(z0 - m), e1 = expf(z1 - m), e2 = expf(z2 - m), e3 = expf(z3 - m);
    float s = e0 + e1 + e2 + e3;
#pragma unroll
    for (int o = 16; o > 0; o >>= 1) s += __shfl_xor_sync(0xffffffffu, s, o);

    float p0 = e0 / s + 1e-14f;
    float p1 = e1 / s + 1e-14f;
    float p2 = e2 / s + 1e-14f;
    float p3 = e3 / s + 1e-14f;

    float4 ov; ov.x = p0; ov.y = p1; ov.z = p2; ov.w = p3;
    *(float4*)&out[(size_t)n * EM + lane * 4] = ov;

    ss[wid][lane * 4 + 0] = p0;
    ss[wid][lane * 4 + 1] = p1;
    ss[wid][lane * 4 + 2] = p2;
    ss[wid][lane * 4 + 3] = p3;
    __syncwarp();

    for (int k = 2; k <= 128; k <<= 1) {
        for (int j = k >> 1; j > 0; j >>= 1) {
#pragma unroll
            for (int t = 0; t < 4; t++) {
                int i  = lane + t * 32;
                int ix = i ^ j;
                if (ix > i) {
                    float a = ss[wid][i], bb = ss[wid][ix];
                    bool desc = ((i & k) == 0);
                    if (desc ? (a < bb) : (a > bb)) { ss[wid][i] = bb; ss[wid][ix] = a; }
                }
            }
            __syncwarp();
        }
    }

    float s0 = ss[wid][lane * 4 + 0];
    float s1 = ss[wid][lane * 4 + 1];
    float s2 = ss[wid][lane * 4 + 2];
    float s3 = ss[wid][lane * 4 + 3];
    float c0 = s0, c1 = c0 + s1, c2 = c1 + s2, c3 = c2 + s3;
    float ex = c3;
#pragma unroll
    for (int o = 1; o < 32; o <<= 1) {
        float t = __shfl_up_sync(0xffffffffu, ex, o);
        if (lane >= o) ex += t;
    }
    ex -= c3;

    int cnt = (ex < THRESH) + (ex + c0 < THRESH) + (ex + c1 < THRESH) + (ex + c2 < THRESH);
    float mg = fminf(fminf(fabsf(ex      - THRESH), fabsf(ex + c0 - THRESH)),
                     fminf(fabsf(ex + c1 - THRESH), fabsf(ex + c2 - THRESH)));
#pragma unroll
    for (int o = 16; o > 0; o >>= 1) {
        cnt += __shfl_xor_sync(0xffffffffu, cnt, o);
        mg = fminf(mg, __shfl_xor_sync(0xffffffffu, mg, o));
    }

    if (lane == 0) {
        if (write_tk) {
            int tk = cnt < actc ? cnt : actc;
            tk_out[n] = (float)tk;
        }
        if (mg < EPS_MARGIN) {
            int p = atomicAdd(&g_nrep, 1);
            g_replist[p] = n;
        }
    }
}

// ---------------- repair: exact fp32 recompute for borderline tokens ----------------
__global__ __launch_bounds__(256)
void gate_repair(const float* __restrict__ x, float* __restrict__ out,
                 float* __restrict__ tk_out, int write_tk) {
    __shared__ float xs[MD];     // 16 KB
    __shared__ float sl[EM];
    __shared__ float sp[EM];
    __shared__ float red[8];
    __shared__ float s_m, s_s;

    const int tid  = threadIdx.x;
    const int lane = tid & 31;
    const int wid  = tid >> 5;
    const int nact = g_nact;
    const int nrep = g_nrep;

    for (int qi = blockIdx.x; qi < nrep; qi += gridDim.x) {
        const int n = g_replist[qi];
        __syncthreads();
        // stage x row
        for (int j = tid * 4; j < MD; j += 1024)
            *(float4*)(xs + j) = *(const float4*)(x + (size_t)n * MD + j);
        __syncthreads();
        // exact fp32 dots: warp w handles experts w, w+8, ...
        for (int e = wid; e < nact; e += 8) {
            const float* wr = g_wc + (size_t)e * MD;
            float a = 0.f;
            for (int j = lane * 4; j < MD; j += 128) {
                float4 wv = *(const float4*)(wr + j);
                a += xs[j] * wv.x + xs[j + 1] * wv.y + xs[j + 2] * wv.z + xs[j + 3] * wv.w;
            }
#pragma unroll
            for (int o = 16; o > 0; o >>= 1) a += __shfl_xor_sync(0xffffffffu, a, o);
            if (lane == 0) sl[e] = a;
        }
        __syncthreads();
        // softmax over active logits
        float vv = (tid < nact) ? sl[tid] : -1e30f;
#pragma unroll
        for (int o = 16; o > 0; o >>= 1) vv = fmaxf(vv, __shfl_xor_sync(0xffffffffu, vv, o));
        if (lane == 0) red[wid] = vv;
        __syncthreads();
        if (tid == 0) {
            float mm = red[0];
            for (int i = 1; i < 8; i++) mm = fmaxf(mm, red[i]);
            s_m = mm;
        }
        __syncthreads();
        float ee = (tid < nact) ? expf(sl[tid] - s_m) : 0.f;
        float sv = ee;
#pragma unroll
        for (int o = 16; o > 0; o >>= 1) sv += __shfl_xor_sync(0xffffffffu, sv, o);
        if (lane == 0) red[wid] = sv;
        __syncthreads();
        if (tid == 0) {
            float t = 0.f;
            for (int i = 0; i < 8; i++) t += red[i];
            s_s = t;
        }
        __syncthreads();
        float p = (tid < nact) ? (ee / s_s + 1e-14f) : 0.f;
        if (tid < nact) sp[tid] = p;
        __syncthreads();
        // write scores row (inactive first, then active overwrite)
        if (tid < EM) out[(size_t)n * EM + tid] = 1e-14f;
        __syncthreads();
        if (tid < nact) out[(size_t)n * EM + g_idx[tid]] = p;
        // adaptive top-k via pairwise exclusive prefix
        float excl = 0.f;
        if (tid < nact) {
            float si = p;
            for (int j = 0; j < nact; j++) {
                float sj = sp[j];
                if (sj > si || (sj == si && j < tid)) excl += sj;
            }
        }
        int fl = (tid < nact && excl < THRESH) ? 1 : 0;
#pragma unroll
        for (int o = 16; o > 0; o >>= 1) fl += __shfl_xor_sync(0xffffffffu, fl, o);
        if (lane == 0) red[wid] = (float)fl;
        __syncthreads();
        if (tid == 0 && write_tk) {
            int c = 0;
            for (int i = 0; i < 8; i++) c += (int)red[i];
            tk_out[n] = (float)(c < nact ? c : nact);
        }
        __syncthreads();
    }
}

extern "C" void kernel_launch(void* const* d_in, const int* in_sizes, int n_in,
                              void* d_out, int out_size) {
    const float* x    = (const float*)d_in[0];
    const float* wg   = (const float*)d_in[1];
    const float* mask = (const float*)d_in[2];
    float* out = (float*)d_out;
    float* tk  = out + (size_t)NT * EM;
    int write_tk = (out_size >= NT * EM + NT) ? 1 : 0;

    const int smem_main = (2 * XBUF + 4 * WBUF) * 4;   // 73,728 B
    cudaFuncSetAttribute((const void*)gemm_mma64,
                         cudaFuncAttributeMaxDynamicSharedMemorySize, smem_main);

    prep_compact<<<1, 128>>>(mask);
    prep_split<<<EM, 256>>>(wg);
    gemm_mma64<<<NT / BM, 256, smem_main>>>(x, out);
    gemm_gate<3><<<NT / BM, 256>>>(x, out);
    gemm_gate<4><<<NT / BM, 256>>>(x, out);
    gate_epilogue<<<NT / 8, 256>>>(mask, out, tk, write_tk);
    gate_repair<<<256, 256>>>(x, out, tk, write_tk);
}

// round 6
// speedup vs baseline: 2.9396x; 1.2927x over previous
#include <cuda_runtime.h>
#include <cuda_fp16.h>
#include <cstdint>

#define NT 16384
#define MD 4096
#define EM 128
#define BM 128
#define BK 32
#define NCHUNK (MD / BK)   // 128
#define THRESH 0.5f
#define EPS_MARGIN 3e-4f

#define XSTF 40                    // X smem row stride (floats)
#define X_STAGE (BM * XSTF)        // 5120 floats
#define WSTH 40                    // W smem row stride (halves)
#define W_STAGE (64 * WSTH)        // 2560 halves

// ---------------- device scratch ----------------
__device__ float  g_wc [EM * MD];    // compacted exact fp32 W (repair + fallback)
__device__ __half g_wh0[EM * MD];    // compacted fp16-hi W
__device__ __half g_wh1[EM * MD];    // compacted fp16-lo W
__device__ int    g_idx[EM];
__device__ int    g_nact;
__device__ int    g_nrep;
__device__ int    g_replist[NT];

// ---------------- helpers ----------------
__device__ __forceinline__ uint32_t smem_u32(const void* p) {
    uint32_t a;
    asm("{ .reg .u64 t; cvta.to.shared.u64 t, %1; cvt.u32.u64 %0, t; }" : "=r"(a) : "l"(p));
    return a;
}

#define CPA16(dst, src) \
    asm volatile("cp.async.cg.shared.global [%0], [%1], 16;" :: "r"(dst), "l"(src))
#define CPA_COMMIT() asm volatile("cp.async.commit_group;" ::: "memory")
#define CPA_WAIT(n)  asm volatile("cp.async.wait_group %0;" :: "n"(n) : "memory")

// fp32 -> (h0, h1) fp16 pair-split, packed as half2 words
__device__ __forceinline__ void split2_f16(float2 v, uint32_t& p0, uint32_t& p1) {
    __half2 a, b;
    a.x = __float2half_rn(v.x);
    a.y = __float2half_rn(v.y);
    b.x = __float2half_rn(v.x - __half2float(a.x));
    b.y = __float2half_rn(v.y - __half2float(a.y));
    p0 = *(uint32_t*)&a;
    p1 = *(uint32_t*)&b;
}

#define MMAF16(D, A, B0, B1)                                                   \
    asm volatile("mma.sync.aligned.m16n8k16.row.col.f32.f16.f16.f32 "          \
        "{%0,%1,%2,%3}, {%4,%5,%6,%7}, {%8,%9}, {%0,%1,%2,%3};"                \
        : "+f"((D)[0]), "+f"((D)[1]), "+f"((D)[2]), "+f"((D)[3])               \
        : "r"((A)[0]), "r"((A)[1]), "r"((A)[2]), "r"((A)[3]), "r"(B0), "r"(B1))

// ---------------- prep 1: mask compaction (+ zero repair queue) ----------------
__global__ void prep_compact(const float* __restrict__ mask) {
    __shared__ int cnts[4];
    int t = threadIdx.x, lane = t & 31, w = t >> 5;   // 128 threads
    bool a = (mask[t] != 0.0f);
    unsigned b = __ballot_sync(0xffffffffu, a);
    if (lane == 0) cnts[w] = __popc(b);
    __syncthreads();
    int ofs = 0;
    for (int i = 0; i < w; i++) ofs += cnts[i];
    if (a) g_idx[ofs + __popc(b & ((1u << lane) - 1u))] = t;
    if (t == 0) {
        g_nact = cnts[0] + cnts[1] + cnts[2] + cnts[3];
        g_nrep = 0;
    }
}

// ---------------- prep 2: compact + fp16 hi/lo split of W ----------------
__global__ __launch_bounds__(256)
void prep_split(const float* __restrict__ wg) {
    int e = blockIdx.x;
    int nact = g_nact;
    int t = threadIdx.x;
    float*  dc = g_wc  + (size_t)e * MD;
    __half* dh = g_wh0 + (size_t)e * MD;
    __half* dl = g_wh1 + (size_t)e * MD;
    if (e < nact) {
        const float* s = wg + (size_t)g_idx[e] * MD;
        for (int j = t * 4; j < MD; j += 1024) {
            float4 v = *(const float4*)(s + j);
            uint32_t h0a, h1a, h0b, h1b;
            split2_f16(make_float2(v.x, v.y), h0a, h1a);
            split2_f16(make_float2(v.z, v.w), h0b, h1b);
            *(float4*)(dc + j) = v;
            *(uint2*)(dh + j) = make_uint2(h0a, h0b);
            *(uint2*)(dl + j) = make_uint2(h1a, h1b);
        }
    } else {
        float4 z = {0.f, 0.f, 0.f, 0.f};
        uint2 zz = {0u, 0u};
        for (int j = t * 4; j < MD; j += 1024) {
            *(float4*)(dc + j) = z;
            *(uint2*)(dh + j) = zz;
            *(uint2*)(dl + j) = zz;
        }
    }
}

// ---------------- main GEMM (nact<=64): fp16x3 via mma.sync m16n8k16 ----------------
__global__ __launch_bounds__(256, 1)
void gemm_f16(const float* __restrict__ x, float* __restrict__ out) {
    const int nact = g_nact;
    if (nact > 64) return;

    extern __shared__ float sm[];
    __shared__ int s_idx[64];
    float*  xs  = sm;                                   // [2][X_STAGE] fp32
    __half* wh0 = (__half*)(sm + 2 * X_STAGE);          // [2][W_STAGE] fp16
    __half* wh1 = wh0 + 2 * W_STAGE;                    // [2][W_STAGE] fp16

    const int tid  = threadIdx.x;           // 256
    const int lane = tid & 31;
    const int wid  = tid >> 5;
    const int gid  = lane >> 2;
    const int tig  = lane & 3;
    const int tok0 = blockIdx.x * BM;

    if (tid < 64) s_idx[tid] = g_idx[tid];

    const int wm = wid & 3, wn = wid >> 2;
    const int mrow = wm * 32;
    const int ncol = wn * 32;

    const uint32_t xsb = smem_u32(xs);
    const uint32_t whb = smem_u32(wh0);
    const uint32_t wlb = smem_u32(wh1);

    float acc_s[2][4][4], acc_h[2][4][4], acc_l[2][4][4];
#pragma unroll
    for (int t = 0; t < 2; t++)
#pragma unroll
        for (int u = 0; u < 4; u++)
#pragma unroll
            for (int r = 0; r < 4; r++) {
                acc_s[t][u][r] = 0.f; acc_h[t][u][r] = 0.f; acc_l[t][u][r] = 0.f;
            }

#define LOAD_CHUNK(i) do {                                                    \
        const int b_ = (i) & 1;                                               \
        const uint32_t xd_ = xsb + b_ * (X_STAGE * 4);                        \
        const float* xsrc_ = x + (size_t)tok0 * MD + (i) * BK;                \
        _Pragma("unroll")                                                     \
        for (int q = 0; q < 4; q++) {                                         \
            int seg = tid + q * 256;                                          \
            int r = seg >> 3, c = seg & 7;                                    \
            CPA16(xd_ + r * (XSTF * 4) + c * 16, xsrc_ + (size_t)r * MD + c * 4); \
        }                                                                     \
        {                                                                     \
            int r = tid >> 2, c = tid & 3;                                    \
            CPA16(whb + b_ * (W_STAGE * 2) + r * (WSTH * 2) + c * 16,         \
                  (const char*)g_wh0 + (size_t)r * (MD * 2) + (i) * (BK * 2) + c * 16); \
            CPA16(wlb + b_ * (W_STAGE * 2) + r * (WSTH * 2) + c * 16,         \
                  (const char*)g_wh1 + (size_t)r * (MD * 2) + (i) * (BK * 2) + c * 16); \
        }                                                                     \
        CPA_COMMIT();                                                         \
    } while (0)

    LOAD_CHUNK(0);
    __syncthreads();

    for (int i = 0; i < NCHUNK; i++) {
        if (i + 1 < NCHUNK) { LOAD_CHUNK(i + 1); CPA_WAIT(1); }
        else                { CPA_WAIT(0); }
        __syncthreads();

        const float*  xb = xs  + (i & 1) * X_STAGE;
        const __half* w0 = wh0 + (i & 1) * W_STAGE;
        const __half* w1 = wh1 + (i & 1) * W_STAGE;

#pragma unroll
        for (int kk = 0; kk < 2; kk++) {
            const int k0 = kk * 16;
            uint32_t ah0[2][4], ah1[2][4];
#pragma unroll
            for (int t = 0; t < 2; t++) {
                const float* base = xb + (mrow + t * 16) * XSTF + k0 + 2 * tig;
                split2_f16(*(const float2*)(base + gid * XSTF),           ah0[t][0], ah1[t][0]);
                split2_f16(*(const float2*)(base + (gid + 8) * XSTF),     ah0[t][1], ah1[t][1]);
                split2_f16(*(const float2*)(base + gid * XSTF + 8),       ah0[t][2], ah1[t][2]);
                split2_f16(*(const float2*)(base + (gid + 8) * XSTF + 8), ah0[t][3], ah1[t][3]);
            }
#pragma unroll
            for (int u = 0; u < 4; u++) {
                const __half* wr = w0 + (ncol + u * 8 + gid) * WSTH + k0 + 2 * tig;
                const __half* wq = w1 + (ncol + u * 8 + gid) * WSTH + k0 + 2 * tig;
                uint32_t b00 = *(const uint32_t*)wr;
                uint32_t b01 = *(const uint32_t*)(wr + 8);
                uint32_t b10 = *(const uint32_t*)wq;
                uint32_t b11 = *(const uint32_t*)(wq + 8);
#pragma unroll
                for (int t = 0; t < 2; t++) {
                    MMAF16(acc_h[t][u], ah0[t], b00, b01);   // h0*w0 -> big acc
                    MMAF16(acc_l[t][u], ah0[t], b10, b11);   // h0*w1 -> small acc
                    MMAF16(acc_l[t][u], ah1[t], b00, b01);   // h1*w0 -> small acc
                }
            }
        }
        if ((i & 7) == 7) {   // drain big accumulator: short rounding chains
#pragma unroll
            for (int t = 0; t < 2; t++)
#pragma unroll
                for (int u = 0; u < 4; u++)
#pragma unroll
                    for (int r = 0; r < 4; r++) {
                        acc_s[t][u][r] += acc_h[t][u][r];
                        acc_h[t][u][r] = 0.f;
                    }
        }
        __syncthreads();
    }

    // scatter raw logits
#pragma unroll
    for (int t = 0; t < 2; t++) {
        const int tokA = tok0 + mrow + t * 16 + gid;
#pragma unroll
        for (int u = 0; u < 4; u++) {
            const int e0 = ncol + u * 8 + tig * 2;
            float v0 = acc_s[t][u][0] + acc_h[t][u][0] + acc_l[t][u][0];
            float v1 = acc_s[t][u][1] + acc_h[t][u][1] + acc_l[t][u][1];
            float v2 = acc_s[t][u][2] + acc_h[t][u][2] + acc_l[t][u][2];
            float v3 = acc_s[t][u][3] + acc_h[t][u][3] + acc_l[t][u][3];
            if (e0 < nact) {
                const int g = s_idx[e0];
                out[(size_t)tokA * EM + g]       = v0;
                out[(size_t)(tokA + 8) * EM + g] = v2;
            }
            if (e0 + 1 < nact) {
                const int g = s_idx[e0 + 1];
                out[(size_t)tokA * EM + g]       = v1;
                out[(size_t)(tokA + 8) * EM + g] = v3;
            }
        }
    }
#undef LOAD_CHUNK
}

// ---------------- fallback GEMM (64 < nact <= 128): exact fp32 FFMA ----------------
template <int EC>
__global__ __launch_bounds__(256, 1)
void gemm_gate(const float* __restrict__ x, float* __restrict__ out) {
    const int nact = g_nact;
    const int ec = (nact + 31) >> 5;
    if (ec != EC || nact <= 64) return;

    __shared__ __align__(16) float xs[BK][132];
    __shared__ __align__(16) float ws[BK][130];
    __shared__ int s_idx[EM];

    const int tid  = threadIdx.x;
    const int lane = tid & 31;
    const int wid  = tid >> 5;
    if (tid < EM) s_idx[tid] = g_idx[tid];

    const int tx = tid & 15, ty = tid >> 4;
    const int tok0 = blockIdx.x * BM;

    float acc[EC][8][2];
#pragma unroll
    for (int c = 0; c < EC; c++)
#pragma unroll
        for (int i = 0; i < 8; i++) { acc[c][i][0] = 0.f; acc[c][i][1] = 0.f; }

    for (int d0 = 0; d0 < MD; d0 += BK) {
        __syncthreads();
#pragma unroll
        for (int r = 0; r < 16; r++) {
            int t = wid * 16 + r;
            xs[lane][t] = x[(size_t)(tok0 + t) * MD + d0 + lane];
        }
#pragma unroll
        for (int r8 = 0; r8 < EC * 4; r8++) {
            int r = wid + r8 * 8;
            ws[lane][r] = (r < nact) ? g_wc[(size_t)r * MD + d0 + lane] : 0.f;
        }
        __syncthreads();
#pragma unroll 8
        for (int dk = 0; dk < BK; dk++) {
            float4 xa = *(const float4*)&xs[dk][ty * 8];
            float4 xb = *(const float4*)&xs[dk][ty * 8 + 4];
#pragma unroll
            for (int c = 0; c < EC; c++) {
                float2 wv = *(const float2*)&ws[dk][c * 32 + tx * 2];
                acc[c][0][0] += xa.x * wv.x; acc[c][0][1] += xa.x * wv.y;
                acc[c][1][0] += xa.y * wv.x; acc[c][1][1] += xa.y * wv.y;
                acc[c][2][0] += xa.z * wv.x; acc[c][2][1] += xa.z * wv.y;
                acc[c][3][0] += xa.w * wv.x; acc[c][3][1] += xa.w * wv.y;
                acc[c][4][0] += xb.x * wv.x; acc[c][4][1] += xb.x * wv.y;
                acc[c][5][0] += xb.y * wv.x; acc[c][5][1] += xb.y * wv.y;
                acc[c][6][0] += xb.z * wv.x; acc[c][6][1] += xb.z * wv.y;
                acc[c][7][0] += xb.w * wv.x; acc[c][7][1] += xb.w * wv.y;
            }
        }
    }
#pragma unroll
    for (int c = 0; c < EC; c++)
#pragma unroll
        for (int j = 0; j < 2; j++) {
            int ce = c * 32 + tx * 2 + j;
            if (ce < nact) {
                int gid = s_idx[ce];
#pragma unroll
                for (int i = 0; i < 8; i++)
                    out[(size_t)(tok0 + ty * 8 + i) * EM + gid] = acc[c][i][j];
            }
        }
}

// ---------------- epilogue: softmax + sort + top-k, flag borderline tokens ----------------
__global__ __launch_bounds__(256)
void gate_epilogue(const float* __restrict__ mask, float* __restrict__ out,
                   float* __restrict__ tk_out, int write_tk) {
    __shared__ float ss[8][128];
    const int lane = threadIdx.x & 31;
    const int wid  = threadIdx.x >> 5;
    const int n = blockIdx.x * 8 + wid;

    float4 v  = *(const float4*)&out[(size_t)n * EM + lane * 4];
    float4 mk = *(const float4*)&mask[lane * 4];

    float z0 = (mk.x != 0.f) ? v.x : -1e9f;
    float z1 = (mk.y != 0.f) ? v.y : -1e9f;
    float z2 = (mk.z != 0.f) ? v.z : -1e9f;
    float z3 = (mk.w != 0.f) ? v.w : -1e9f;

    int actc = (mk.x != 0.f) + (mk.y != 0.f) + (mk.z != 0.f) + (mk.w != 0.f);
#pragma unroll
    for (int o = 16; o > 0; o >>= 1) actc += __shfl_xor_sync(0xffffffffu, actc, o);

    float m = fmaxf(fmaxf(z0, z1), fmaxf(z2, z3));
#pragma unroll
    for (int o = 16; o > 0; o >>= 1) m = fmaxf(m, __shfl_xor_sync(0xffffffffu, m, o));

    float e0 = expf(z0 - m), e1 = expf(z1 - m), e2 = expf(z2 - m), e3 = expf(z3 - m);
    float s = e0 + e1 + e2 + e3;
#pragma unroll
    for (int o = 16; o > 0; o >>= 1) s += __shfl_xor_sync(0xffffffffu, s, o);

    float p0 = e0 / s + 1e-14f;
    float p1 = e1 / s + 1e-14f;
    float p2 = e2 / s + 1e-14f;
    float p3 = e3 / s + 1e-14f;

    float4 ov; ov.x = p0; ov.y = p1; ov.z = p2; ov.w = p3;
    *(float4*)&out[(size_t)n * EM + lane * 4] = ov;

    ss[wid][lane * 4 + 0] = p0;
    ss[wid][lane * 4 + 1] = p1;
    ss[wid][lane * 4 + 2] = p2;
    ss[wid][lane * 4 + 3] = p3;
    __syncwarp();

    for (int k = 2; k <= 128; k <<= 1) {
        for (int j = k >> 1; j > 0; j >>= 1) {
#pragma unroll
            for (int t = 0; t < 4; t++) {
                int i  = lane + t * 32;
                int ix = i ^ j;
                if (ix > i) {
                    float a = ss[wid][i], bb = ss[wid][ix];
                    bool desc = ((i & k) == 0);
                    if (desc ? (a < bb) : (a > bb)) { ss[wid][i] = bb; ss[wid][ix] = a; }
                }
            }
            __syncwarp();
        }
    }

    float s0 = ss[wid][lane * 4 + 0];
    float s1 = ss[wid][lane * 4 + 1];
    float s2 = ss[wid][lane * 4 + 2];
    float s3 = ss[wid][lane * 4 + 3];
    float c0 = s0, c1 = c0 + s1, c2 = c1 + s2, c3 = c2 + s3;
    float ex = c3;
#pragma unroll
    for (int o = 1; o < 32; o <<= 1) {
        float t = __shfl_up_sync(0xffffffffu, ex, o);
        if (lane >= o) ex += t;
    }
    ex -= c3;

    int cnt = (ex < THRESH) + (ex + c0 < THRESH) + (ex + c1 < THRESH) + (ex + c2 < THRESH);
    float mg = fminf(fminf(fabsf(ex      - THRESH), fabsf(ex + c0 - THRESH)),
                     fminf(fabsf(ex + c1 - THRESH), fabsf(ex + c2 - THRESH)));
#pragma unroll
    for (int o = 16; o > 0; o >>= 1) {
        cnt += __shfl_xor_sync(0xffffffffu, cnt, o);
        mg = fminf(mg, __shfl_xor_sync(0xffffffffu, mg, o));
    }

    if (lane == 0) {
        if (write_tk) {
            int tk = cnt < actc ? cnt : actc;
            tk_out[n] = (float)tk;
        }
        if (mg < EPS_MARGIN) {
            int p = atomicAdd(&g_nrep, 1);
            g_replist[p] = n;
        }
    }
}

// ---------------- repair: exact fp32 recompute for borderline tokens ----------------
__global__ __launch_bounds__(256)
void gate_repair(const float* __restrict__ x, float* __restrict__ out,
                 float* __restrict__ tk_out, int write_tk) {
    __shared__ float xs[MD];
    __shared__ float sl[EM];
    __shared__ float sp[EM];
    __shared__ float red[8];
    __shared__ float s_m, s_s;

    const int tid  = threadIdx.x;
    const int lane = tid & 31;
    const int wid  = tid >> 5;
    const int nact = g_nact;
    const int nrep = g_nrep;

    for (int qi = blockIdx.x; qi < nrep; qi += gridDim.x) {
        const int n = g_replist[qi];
        __syncthreads();
        for (int j = tid * 4; j < MD; j += 1024)
            *(float4*)(xs + j) = *(const float4*)(x + (size_t)n * MD + j);
        __syncthreads();
        for (int e = wid; e < nact; e += 8) {
            const float* wr = g_wc + (size_t)e * MD;
            float a = 0.f;
            for (int j = lane * 4; j < MD; j += 128) {
                float4 wv = *(const float4*)(wr + j);
                a += xs[j] * wv.x + xs[j + 1] * wv.y + xs[j + 2] * wv.z + xs[j + 3] * wv.w;
            }
#pragma unroll
            for (int o = 16; o > 0; o >>= 1) a += __shfl_xor_sync(0xffffffffu, a, o);
            if (lane == 0) sl[e] = a;
        }
        __syncthreads();
        float vv = (tid < nact) ? sl[tid] : -1e30f;
#pragma unroll
        for (int o = 16; o > 0; o >>= 1) vv = fmaxf(vv, __shfl_xor_sync(0xffffffffu, vv, o));
        if (lane == 0) red[wid] = vv;
        __syncthreads();
        if (tid == 0) {
            float mm = red[0];
            for (int i = 1; i < 8; i++) mm = fmaxf(mm, red[i]);
            s_m = mm;
        }
        __syncthreads();
        float ee = (tid < nact) ? expf(sl[tid] - s_m) : 0.f;
        float sv = ee;
#pragma unroll
        for (int o = 16; o > 0; o >>= 1) sv += __shfl_xor_sync(0xffffffffu, sv, o);
        if (lane == 0) red[wid] = sv;
        __syncthreads();
        if (tid == 0) {
            float t = 0.f;
            for (int i = 0; i < 8; i++) t += red[i];
            s_s = t;
        }
        __syncthreads();
        float p = (tid < nact) ? (ee / s_s + 1e-14f) : 0.f;
        if (tid < nact) sp[tid] = p;
        __syncthreads();
        if (tid < EM) out[(size_t)n * EM + tid] = 1e-14f;
        __syncthreads();
        if (tid < nact) out[(size_t)n * EM + g_idx[tid]] = p;
        float excl = 0.f;
        if (tid < nact) {
            float si = p;
            for (int j = 0; j < nact; j++) {
                float sj = sp[j];
                if (sj > si || (sj == si && j < tid)) excl += sj;
            }
        }
        int fl = (tid < nact && excl < THRESH) ? 1 : 0;
#pragma unroll
        for (int o = 16; o > 0; o >>= 1) fl += __shfl_xor_sync(0xffffffffu, fl, o);
        if (lane == 0) red[wid] = (float)fl;
        __syncthreads();
        if (tid == 0 && write_tk) {
            int c = 0;
            for (int i = 0; i < 8; i++) c += (int)red[i];
            tk_out[n] = (float)(c < nact ? c : nact);
        }
        __syncthreads();
    }
}

extern "C" void kernel_launch(void* const* d_in, const int* in_sizes, int n_in,
                              void* d_out, int out_size) {
    const float* x    = (const float*)d_in[0];
    const float* wg   = (const float*)d_in[1];
    const float* mask = (const float*)d_in[2];
    float* out = (float*)d_out;
    float* tk  = out + (size_t)NT * EM;
    int write_tk = (out_size >= NT * EM + NT) ? 1 : 0;

    const int smem_main = 2 * X_STAGE * 4 + 4 * W_STAGE * 2;   // 61,440 B
    cudaFuncSetAttribute((const void*)gemm_f16,
                         cudaFuncAttributeMaxDynamicSharedMemorySize, smem_main);

    prep_compact<<<1, 128>>>(mask);
    prep_split<<<EM, 256>>>(wg);
    gemm_f16<<<NT / BM, 256, smem_main>>>(x, out);
    gemm_gate<3><<<NT / BM, 256>>>(x, out);
    gemm_gate<4><<<NT / BM, 256>>>(x, out);
    gate_epilogue<<<NT / 8, 256>>>(mask, out, tk, write_tk);
    gate_repair<<<256, 256>>>(x, out, tk, write_tk);
}